// round 1
// baseline (speedup 1.0000x reference)
#include <cuda_runtime.h>
#include <cuda_bf16.h>
#include <math.h>

// QuantumLayer: B x 4-qubit circuit.
//   state0 = P * m   (product state from RX(x_q);  m real, P = diag((-i)^popcount))
//   final  = U * state0, U = 3 layers of [RX(w_lq) x4 ; CNOT ring] (batch-constant)
//   out_q  = signed sum over |final|^2
// Fold A = U*P (computed once per launch from weights). Per element:
//   m (16 real) -> y_re = Ar*m, y_im = Ai*m -> p = y_re^2+y_im^2 -> Walsh sums.

#define DIM 16

// A stored as 512 floats: rows 0..15 = Re rows (16 floats each), rows 16..31 = Im rows.
__device__ __align__(16) float g_A[512];

// ---------------------------------------------------------------------------
// Kernel 1: build A = U * P from weights (12 floats). 16 threads, one column each.
// ---------------------------------------------------------------------------
__global__ void build_A_kernel(const float* __restrict__ w) {
    int j = threadIdx.x;
    if (j >= 16) return;

    float vr[16], vi[16];
#pragma unroll
    for (int i = 0; i < 16; i++) { vr[i] = 0.0f; vi[i] = 0.0f; }

    // Column j of P: (-i)^popcount(j)
    int pc = __popc(j) & 3;
    vr[j] = (pc == 0) ? 1.0f : ((pc == 2) ? -1.0f : 0.0f);
    vi[j] = (pc == 1) ? -1.0f : ((pc == 3) ? 1.0f : 0.0f);

#pragma unroll
    for (int l = 0; l < 3; l++) {
        // RX(w[l][q]) on qubit q (qubit q <-> bit (3-q))
#pragma unroll
        for (int q = 0; q < 4; q++) {
            float sq, cq;
            sincosf(0.5f * w[l * 4 + q], &sq, &cq);
            const int bit = 1 << (3 - q);
#pragma unroll
            for (int i = 0; i < 16; i++) {
                if (i & bit) continue;
                const int i1 = i | bit;
                float ar = vr[i],  ai = vi[i];
                float br = vr[i1], bi = vi[i1];
                // new0 = c*a + (-i s)*b ; new1 = (-i s)*a + c*b
                vr[i]  = cq * ar + sq * bi;
                vi[i]  = cq * ai - sq * br;
                vr[i1] = cq * br + sq * ai;
                vi[i1] = cq * bi - sq * ar;
            }
        }
        // CNOT(control=q, target=(q+1)%4): swap v[i] <-> v[i^tbit] where ctrl bit set
#pragma unroll
        for (int q = 0; q < 4; q++) {
            const int pcb = 3 - q;
            const int ptb = 3 - ((q + 1) & 3);
#pragma unroll
            for (int i = 0; i < 16; i++) {
                if (((i >> pcb) & 1) == 0) continue;
                if ((i >> ptb) & 1) continue;
                const int i2 = i | (1 << ptb);
                float tr = vr[i], ti = vi[i];
                vr[i] = vr[i2]; vi[i] = vi[i2];
                vr[i2] = tr;    vi[i2] = ti;
            }
        }
    }

#pragma unroll
    for (int i = 0; i < 16; i++) {
        g_A[i * 16 + j]       = vr[i];   // Re row i
        g_A[256 + i * 16 + j] = vi[i];   // Im row i
    }
}

// ---------------------------------------------------------------------------
// Kernel 2: main batch kernel. 2 elements per thread.
// ---------------------------------------------------------------------------
__device__ __forceinline__ void build_m(const float4 xv, float m[16]) {
    float c[4], s[4];
    __sincosf(0.5f * xv.x, &s[0], &c[0]);
    __sincosf(0.5f * xv.y, &s[1], &c[1]);
    __sincosf(0.5f * xv.z, &s[2], &c[2]);
    __sincosf(0.5f * xv.w, &s[3], &c[3]);
    float t4[4];
    t4[0] = c[0] * c[1]; t4[1] = c[0] * s[1];
    t4[2] = s[0] * c[1]; t4[3] = s[0] * s[1];
    float t8[8];
#pragma unroll
    for (int k = 0; k < 4; k++) { t8[2 * k] = t4[k] * c[2]; t8[2 * k + 1] = t4[k] * s[2]; }
#pragma unroll
    for (int k = 0; k < 8; k++) { m[2 * k] = t8[k] * c[3]; m[2 * k + 1] = t8[k] * s[3]; }
}

__device__ __forceinline__ float4 walsh4(const float p[16]) {
    float e8[8], o3 = 0.0f;
#pragma unroll
    for (int k = 0; k < 8; k++) {
        e8[k] = p[2 * k] + p[2 * k + 1];
        o3   += p[2 * k] - p[2 * k + 1];
    }
    float e4[4], o2 = 0.0f;
#pragma unroll
    for (int k = 0; k < 4; k++) {
        e4[k] = e8[2 * k] + e8[2 * k + 1];
        o2   += e8[2 * k] - e8[2 * k + 1];
    }
    float o1 = (e4[0] - e4[1]) + (e4[2] - e4[3]);
    float o0 = (e4[0] + e4[1]) - (e4[2] + e4[3]);
    return make_float4(o0, o1, o2, o3);
}

__global__ __launch_bounds__(256) void qlayer_kernel(
    const float* __restrict__ x, float* __restrict__ out, int B)
{
    __shared__ __align__(16) float shA[512];
    const int t = threadIdx.x;
    shA[t]       = g_A[t];
    shA[t + 256] = g_A[t + 256];
    __syncthreads();

    const long long e0 = ((long long)blockIdx.x * 256 + t) * 2;
    if (e0 >= B) return;
    const bool has1 = (e0 + 1) < B;

    const float4* __restrict__ x4 = (const float4*)x;
    float4 xv0 = x4[e0];
    float4 xv1 = has1 ? x4[e0 + 1] : xv0;

    float m0[16], m1[16];
    build_m(xv0, m0);
    build_m(xv1, m1);

    const float4* __restrict__ A4 = (const float4*)shA;  // [0..63]=Re rows, [64..127]=Im rows
    float p0[16], p1[16];

#pragma unroll
    for (int i = 0; i < 16; i++) {
        float4 r0 = A4[i * 4 + 0], r1 = A4[i * 4 + 1], r2 = A4[i * 4 + 2], r3 = A4[i * 4 + 3];
        float yr0 = r0.x * m0[0]  + r0.y * m0[1]  + r0.z * m0[2]  + r0.w * m0[3]
                  + r1.x * m0[4]  + r1.y * m0[5]  + r1.z * m0[6]  + r1.w * m0[7]
                  + r2.x * m0[8]  + r2.y * m0[9]  + r2.z * m0[10] + r2.w * m0[11]
                  + r3.x * m0[12] + r3.y * m0[13] + r3.z * m0[14] + r3.w * m0[15];
        float yr1 = r0.x * m1[0]  + r0.y * m1[1]  + r0.z * m1[2]  + r0.w * m1[3]
                  + r1.x * m1[4]  + r1.y * m1[5]  + r1.z * m1[6]  + r1.w * m1[7]
                  + r2.x * m1[8]  + r2.y * m1[9]  + r2.z * m1[10] + r2.w * m1[11]
                  + r3.x * m1[12] + r3.y * m1[13] + r3.z * m1[14] + r3.w * m1[15];

        float4 q0 = A4[64 + i * 4 + 0], q1 = A4[64 + i * 4 + 1],
               q2 = A4[64 + i * 4 + 2], q3 = A4[64 + i * 4 + 3];
        float yi0 = q0.x * m0[0]  + q0.y * m0[1]  + q0.z * m0[2]  + q0.w * m0[3]
                  + q1.x * m0[4]  + q1.y * m0[5]  + q1.z * m0[6]  + q1.w * m0[7]
                  + q2.x * m0[8]  + q2.y * m0[9]  + q2.z * m0[10] + q2.w * m0[11]
                  + q3.x * m0[12] + q3.y * m0[13] + q3.z * m0[14] + q3.w * m0[15];
        float yi1 = q0.x * m1[0]  + q0.y * m1[1]  + q0.z * m1[2]  + q0.w * m1[3]
                  + q1.x * m1[4]  + q1.y * m1[5]  + q1.z * m1[6]  + q1.w * m1[7]
                  + q2.x * m1[8]  + q2.y * m1[9]  + q2.z * m1[10] + q2.w * m1[11]
                  + q3.x * m1[12] + q3.y * m1[13] + q3.z * m1[14] + q3.w * m1[15];

        p0[i] = yr0 * yr0 + yi0 * yi0;
        p1[i] = yr1 * yr1 + yi1 * yi1;
    }

    float4* __restrict__ o4 = (float4*)out;
    o4[e0] = walsh4(p0);
    if (has1) o4[e0 + 1] = walsh4(p1);
}

// ---------------------------------------------------------------------------
extern "C" void kernel_launch(void* const* d_in, const int* in_sizes, int n_in,
                              void* d_out, int out_size) {
    // Inputs: x (B*4 floats), weights (12 floats). Defensive order check.
    const float* xp = (const float*)d_in[0];
    const float* wp = (const float*)d_in[1];
    int sx = in_sizes[0];
    if (n_in >= 2 && in_sizes[0] == 12 && in_sizes[1] != 12) {
        xp = (const float*)d_in[1];
        wp = (const float*)d_in[0];
        sx = in_sizes[1];
    }
    const int B = sx / 4;

    build_A_kernel<<<1, 16>>>(wp);

    const int elems_per_block = 256 * 2;
    const int grid = (B + elems_per_block - 1) / elems_per_block;
    qlayer_kernel<<<grid, 256>>>(xp, (float*)d_out, B);
}

// round 2
// speedup vs baseline: 1.0091x; 1.0091x over previous
#include <cuda_runtime.h>
#include <cuda_bf16.h>
#include <math.h>

// QuantumLayer: fold the batch-constant circuit into A = U*P (16x16 complex).
// Per element: m (16 real, product state) -> y = A m -> p_i = |y_i|^2 -> 4 Walsh sums.
// This version packs 2 elements per f32x2 lane-pair (4 elements/thread) and uses
// fma.rn.f32x2 to halve fma-pipe instruction count (the measured bottleneck).

typedef unsigned long long u64;

#define FMA2(d, a, b, c) asm("fma.rn.f32x2 %0, %1, %2, %3;" : "=l"(d) : "l"(a), "l"(b), "l"(c))
#define MUL2(d, a, b)    asm("mul.rn.f32x2 %0, %1, %2;"      : "=l"(d) : "l"(a), "l"(b))
#define ADD2(d, a, b)    asm("add.rn.f32x2 %0, %1, %2;"      : "=l"(d) : "l"(a), "l"(b))
#define PACK2(d, lo, hi) asm("mov.b64 %0, {%1, %2};"         : "=l"(d) : "f"(lo), "f"(hi))
#define UNPACK2(lo, hi, v) asm("mov.b64 {%0, %1}, %2;" : "=f"(lo), "=f"(hi) : "l"(v))

// A stored as 512 floats: [0:256) Re rows (16 floats each), [256:512) Im rows.
__device__ __align__(16) float g_A[512];

// ---------------------------------------------------------------------------
// Kernel 1: build A = U * P from weights (12 floats). 16 threads, one column each.
// ---------------------------------------------------------------------------
__global__ void build_A_kernel(const float* __restrict__ w) {
    int j = threadIdx.x;
    if (j >= 16) return;

    float vr[16], vi[16];
#pragma unroll
    for (int i = 0; i < 16; i++) { vr[i] = 0.0f; vi[i] = 0.0f; }

    // Column j of P: (-i)^popcount(j)
    int pc = __popc(j) & 3;
    vr[j] = (pc == 0) ? 1.0f : ((pc == 2) ? -1.0f : 0.0f);
    vi[j] = (pc == 1) ? -1.0f : ((pc == 3) ? 1.0f : 0.0f);

#pragma unroll
    for (int l = 0; l < 3; l++) {
#pragma unroll
        for (int q = 0; q < 4; q++) {
            float sq, cq;
            sincosf(0.5f * w[l * 4 + q], &sq, &cq);
            const int bit = 1 << (3 - q);
#pragma unroll
            for (int i = 0; i < 16; i++) {
                if (i & bit) continue;
                const int i1 = i | bit;
                float ar = vr[i],  ai = vi[i];
                float br = vr[i1], bi = vi[i1];
                vr[i]  = cq * ar + sq * bi;
                vi[i]  = cq * ai - sq * br;
                vr[i1] = cq * br + sq * ai;
                vi[i1] = cq * bi - sq * ar;
            }
        }
#pragma unroll
        for (int q = 0; q < 4; q++) {
            const int pcb = 3 - q;
            const int ptb = 3 - ((q + 1) & 3);
#pragma unroll
            for (int i = 0; i < 16; i++) {
                if (((i >> pcb) & 1) == 0) continue;
                if ((i >> ptb) & 1) continue;
                const int i2 = i | (1 << ptb);
                float tr = vr[i], ti = vi[i];
                vr[i] = vr[i2]; vi[i] = vi[i2];
                vr[i2] = tr;    vi[i2] = ti;
            }
        }
    }

#pragma unroll
    for (int i = 0; i < 16; i++) {
        g_A[i * 16 + j]       = vr[i];
        g_A[256 + i * 16 + j] = vi[i];
    }
}

// ---------------------------------------------------------------------------
// Kernel 2: 4 elements per thread, packed as two f32x2 pairs.
// ---------------------------------------------------------------------------
struct __align__(16) U2 { u64 a, b; };

// Build packed m[16] for one element pair from packed per-qubit cos/sin.
__device__ __forceinline__ void build_m_pair(const u64 c[4], const u64 s[4], u64 m[16]) {
    u64 t4[4], t8[8];
    MUL2(t4[0], c[0], c[1]); MUL2(t4[1], c[0], s[1]);
    MUL2(t4[2], s[0], c[1]); MUL2(t4[3], s[0], s[1]);
#pragma unroll
    for (int k = 0; k < 4; k++) { MUL2(t8[2*k], t4[k], c[2]); MUL2(t8[2*k+1], t4[k], s[2]); }
#pragma unroll
    for (int k = 0; k < 8; k++) { MUL2(m[2*k], t8[k], c[3]); MUL2(m[2*k+1], t8[k], s[3]); }
}

__global__ __launch_bounds__(256, 2) void qlayer_kernel(
    const float* __restrict__ x, float* __restrict__ out, int B)
{
    // A duplicated: shA[2k] = shA[2k+1] = A[k]  (4 KB). One LDS.128 = 2 packed coefs.
    __shared__ __align__(16) float shA[1024];
    const int t = threadIdx.x;
    {
        float a = g_A[t];        shA[2*t]           = a; shA[2*t+1]           = a;
        float b = g_A[t + 256];  shA[2*(t+256)]     = b; shA[2*(t+256)+1]     = b;
    }
    __syncthreads();

    const long long e0 = ((long long)blockIdx.x * 256 + t) * 4;
    if (e0 >= B) return;

    // Load x for 4 elements (clamped for tail).
    const float4* __restrict__ x4 = (const float4*)x;
    float xa[4][4];
#pragma unroll
    for (int el = 0; el < 4; el++) {
        long long ei = e0 + el; if (ei >= B) ei = B - 1;
        float4 v = x4[ei];
        xa[el][0] = v.x; xa[el][1] = v.y; xa[el][2] = v.z; xa[el][3] = v.w;
    }

    // Per-element half-angle cos/sin, then pack per qubit into pairs (01) and (23).
    float C[4][4], S[4][4];
#pragma unroll
    for (int el = 0; el < 4; el++)
#pragma unroll
        for (int q = 0; q < 4; q++)
            __sincosf(0.5f * xa[el][q], &S[el][q], &C[el][q]);

    u64 c01[4], s01[4], c23[4], s23[4];
#pragma unroll
    for (int q = 0; q < 4; q++) {
        PACK2(c01[q], C[0][q], C[1][q]); PACK2(s01[q], S[0][q], S[1][q]);
        PACK2(c23[q], C[2][q], C[3][q]); PACK2(s23[q], S[2][q], S[3][q]);
    }

    u64 m01[16], m23[16];
    build_m_pair(c01, s01, m01);
    build_m_pair(c23, s23, m23);

    const U2* __restrict__ Are = (const U2*)shA;          // rows 0..15, 8 U2 each
    const U2* __restrict__ Aim = (const U2*)(shA + 512);

    const u64 NEG1 = 0xBF800000BF800000ULL;  // packed {-1.f, -1.f}
    u64 w01[4], w23[4];

#pragma unroll
    for (int i = 0; i < 16; i++) {
        u64 yr01, yr23, yi01, yi23;
        {
            U2 v = Are[i * 8];
            MUL2(yr01, v.a, m01[0]);  MUL2(yr23, v.a, m23[0]);
            FMA2(yr01, v.b, m01[1], yr01); FMA2(yr23, v.b, m23[1], yr23);
        }
#pragma unroll
        for (int e = 1; e < 8; e++) {
            U2 v = Are[i * 8 + e];
            FMA2(yr01, v.a, m01[2*e],   yr01); FMA2(yr23, v.a, m23[2*e],   yr23);
            FMA2(yr01, v.b, m01[2*e+1], yr01); FMA2(yr23, v.b, m23[2*e+1], yr23);
        }
        {
            U2 v = Aim[i * 8];
            MUL2(yi01, v.a, m01[0]);  MUL2(yi23, v.a, m23[0]);
            FMA2(yi01, v.b, m01[1], yi01); FMA2(yi23, v.b, m23[1], yi23);
        }
#pragma unroll
        for (int e = 1; e < 8; e++) {
            U2 v = Aim[i * 8 + e];
            FMA2(yi01, v.a, m01[2*e],   yi01); FMA2(yi23, v.a, m23[2*e],   yi23);
            FMA2(yi01, v.b, m01[2*e+1], yi01); FMA2(yi23, v.b, m23[2*e+1], yi23);
        }

        u64 p01, p23, tq0, tq1;
        MUL2(tq0, yr01, yr01); FMA2(p01, yi01, yi01, tq0);
        MUL2(tq1, yr23, yr23); FMA2(p23, yi23, yi23, tq1);

        if (i == 0) {
#pragma unroll
            for (int q = 0; q < 4; q++) { w01[q] = p01; w23[q] = p23; }
        } else {
#pragma unroll
            for (int q = 0; q < 4; q++) {
                if ((i >> (3 - q)) & 1) {
                    FMA2(w01[q], p01, NEG1, w01[q]);
                    FMA2(w23[q], p23, NEG1, w23[q]);
                } else {
                    ADD2(w01[q], w01[q], p01);
                    ADD2(w23[q], w23[q], p23);
                }
            }
        }
    }

    // Unpack + store.
    float o[4][4];
#pragma unroll
    for (int q = 0; q < 4; q++) {
        UNPACK2(o[0][q], o[1][q], w01[q]);
        UNPACK2(o[2][q], o[3][q], w23[q]);
    }
    float4* __restrict__ o4 = (float4*)out;
#pragma unroll
    for (int el = 0; el < 4; el++) {
        long long ei = e0 + el;
        if (ei < B) o4[ei] = make_float4(o[el][0], o[el][1], o[el][2], o[el][3]);
    }
}

// ---------------------------------------------------------------------------
extern "C" void kernel_launch(void* const* d_in, const int* in_sizes, int n_in,
                              void* d_out, int out_size) {
    const float* xp = (const float*)d_in[0];
    const float* wp = (const float*)d_in[1];
    int sx = in_sizes[0];
    if (n_in >= 2 && in_sizes[0] == 12 && in_sizes[1] != 12) {
        xp = (const float*)d_in[1];
        wp = (const float*)d_in[0];
        sx = in_sizes[1];
    }
    const int B = sx / 4;

    build_A_kernel<<<1, 16>>>(wp);

    const int elems_per_block = 256 * 4;
    const int grid = (B + elems_per_block - 1) / elems_per_block;
    qlayer_kernel<<<grid, 256>>>(xp, (float*)d_out, B);
}

// round 3
// speedup vs baseline: 1.3927x; 1.3801x over previous
#include <cuda_runtime.h>
#include <cuda_bf16.h>
#include <math.h>

// QuantumLayer collapsed to a multilinear polynomial:
//   out_o(x) = T[o] . (1,cos x0,sin x0) x (1,cos x1,sin x1) x (1,cos x2,sin x2) x (1,cos x3,sin x3)
// Exact identity: every output is a quadratic form in the product-state vector m,
// and per-qubit pair products {c^2, cs, s^2} (half-angle) are affine in (1,cos,sin)
// (full angle). T (4 x 3^4) is batch-constant: built by sampling the reference
// circuit at 81 angle tuples {0, pi/2, pi}^4 and inverting the 3x3 Vandermonde
// per axis. Hot kernel: 4 sincos + 320 FMA per element. No matvec, no Walsh.

__device__ __align__(16) float g_T[432];  // [o][k0][k1][k2][k3 padded to 4]

// ---------------------------------------------------------------------------
// Kernel 1: build T from weights (12 floats).
// Phase A (81 thr): simulate circuit at sample tuple, compute 4 outputs.
// Phase B (324 thr): inverse-Vandermonde transform along each of 4 axes.
// Phase C (432 thr): write padded T to global.
// ---------------------------------------------------------------------------
__global__ void build_T_kernel(const float* __restrict__ w) {
    __shared__ float bufA[324], bufB[324];
    const int t = threadIdx.x;

    if (t < 81) {
        const float ang[3] = {0.0f, 1.5707963267948966f, 3.1415926535897931f};
        const int a0 = t / 27, a1 = (t / 9) % 3, a2 = (t / 3) % 3, a3 = t % 3;
        const float xa[4] = {ang[a0], ang[a1], ang[a2], ang[a3]};

        float vr[16], vi[16];
#pragma unroll
        for (int i = 0; i < 16; i++) { vr[i] = 0.0f; vi[i] = 0.0f; }
        vr[0] = 1.0f;

        // Initial RX(x_q) gates (qubit q <-> bit 3-q).
#pragma unroll
        for (int q = 0; q < 4; q++) {
            float sq, cq; sincosf(0.5f * xa[q], &sq, &cq);
            const int bit = 1 << (3 - q);
#pragma unroll
            for (int i = 0; i < 16; i++) {
                if (i & bit) continue;
                const int i1 = i | bit;
                float ar = vr[i], ai = vi[i], br = vr[i1], bi = vi[i1];
                vr[i]  = cq * ar + sq * bi;  vi[i]  = cq * ai - sq * br;
                vr[i1] = cq * br + sq * ai;  vi[i1] = cq * bi - sq * ar;
            }
        }
        // 3 layers: RX(w) x4 then CNOT ring.
#pragma unroll
        for (int l = 0; l < 3; l++) {
#pragma unroll
            for (int q = 0; q < 4; q++) {
                float sq, cq; sincosf(0.5f * w[l * 4 + q], &sq, &cq);
                const int bit = 1 << (3 - q);
#pragma unroll
                for (int i = 0; i < 16; i++) {
                    if (i & bit) continue;
                    const int i1 = i | bit;
                    float ar = vr[i], ai = vi[i], br = vr[i1], bi = vi[i1];
                    vr[i]  = cq * ar + sq * bi;  vi[i]  = cq * ai - sq * br;
                    vr[i1] = cq * br + sq * ai;  vi[i1] = cq * bi - sq * ar;
                }
            }
#pragma unroll
            for (int q = 0; q < 4; q++) {
                const int pcb = 3 - q;
                const int ptb = 3 - ((q + 1) & 3);
#pragma unroll
                for (int i = 0; i < 16; i++) {
                    if (((i >> pcb) & 1) == 0) continue;
                    if ((i >> ptb) & 1) continue;
                    const int i2 = i | (1 << ptb);
                    float tr = vr[i], ti = vi[i];
                    vr[i] = vr[i2]; vi[i] = vi[i2];
                    vr[i2] = tr;    vi[i2] = ti;
                }
            }
        }

        float p[16];
#pragma unroll
        for (int i = 0; i < 16; i++) p[i] = vr[i] * vr[i] + vi[i] * vi[i];
#pragma unroll
        for (int q = 0; q < 4; q++) {
            float s = 0.0f;
#pragma unroll
            for (int i = 0; i < 16; i++)
                s += ((i >> (3 - q)) & 1) ? -p[i] : p[i];
            bufA[q * 81 + t] = s;
        }
    }
    __syncthreads();

    // Inverse Vandermonde: basis (1, cos, sin) sampled at x in {0, pi/2, pi}
    //   c0 = (s0+s2)/2 ; c1 = (s0-s2)/2 ; c2 = s1 - (s0+s2)/2
    const float Vi[3][3] = {{0.5f, 0.0f, 0.5f},
                            {0.5f, 0.0f, -0.5f},
                            {-0.5f, 1.0f, -0.5f}};
    const int WST[4] = {27, 9, 3, 1};
    float* src = bufA;
    float* dst = bufB;
    for (int ax = 3; ax >= 0; ax--) {
        if (t < 324) {
            const int o = t / 81, e = t % 81;
            const int ws = WST[ax];
            const int k = (e / ws) % 3;
            const int eb = e - k * ws;
            const float* s = src + o * 81;
            dst[t] = Vi[k][0] * s[eb] + Vi[k][1] * s[eb + ws] + Vi[k][2] * s[eb + 2 * ws];
        }
        __syncthreads();
        float* tmp = src; src = dst; dst = tmp;
    }

    if (t < 432) {
        const int o = t / 108, r = t % 108, k012 = r / 4, c = r % 4;
        g_T[t] = (c < 3) ? src[o * 81 + k012 * 3 + c] : 0.0f;
    }
}

// ---------------------------------------------------------------------------
// Kernel 2: 4 elements/thread. Nested Horner contraction, 320 FMA/element.
// ---------------------------------------------------------------------------
__global__ __launch_bounds__(256) void qlayer_kernel(
    const float* __restrict__ x, float* __restrict__ out, int B)
{
    __shared__ __align__(16) float4 shT[108];   // [o*27 + k0*9 + k1*3 + k2], .xyz = k3
    const int t = threadIdx.x;
    if (t < 108) shT[t] = ((const float4*)g_T)[t];
    __syncthreads();

    const long long e0 = ((long long)blockIdx.x * 256 + t) * 4;
    if (e0 >= B) return;

    const float4* __restrict__ x4 = (const float4*)x;
    float C[4][4], S[4][4];   // [el][qubit], full-angle cos/sin
#pragma unroll
    for (int el = 0; el < 4; el++) {
        long long ei = e0 + el; if (ei >= B) ei = B - 1;
        float4 v = x4[ei];
        __sincosf(v.x, &S[el][0], &C[el][0]);
        __sincosf(v.y, &S[el][1], &C[el][1]);
        __sincosf(v.z, &S[el][2], &C[el][2]);
        __sincosf(v.w, &S[el][3], &C[el][3]);
    }

    float outv[4][4];  // [el][o]
#pragma unroll
    for (int o = 0; o < 4; o++) {
        float acc[4];
#pragma unroll
        for (int k0 = 0; k0 < 3; k0++) {
            float Aacc[4];
#pragma unroll
            for (int k1 = 0; k1 < 3; k1++) {
                float Bacc[4];
#pragma unroll
                for (int k2 = 0; k2 < 3; k2++) {
                    const float4 tq = shT[o * 27 + k0 * 9 + k1 * 3 + k2];
#pragma unroll
                    for (int el = 0; el < 4; el++) {
                        float D = fmaf(tq.z, S[el][3], fmaf(tq.y, C[el][3], tq.x));
                        if (k2 == 0)      Bacc[el] = D;
                        else if (k2 == 1) Bacc[el] = fmaf(C[el][2], D, Bacc[el]);
                        else              Bacc[el] = fmaf(S[el][2], D, Bacc[el]);
                    }
                }
#pragma unroll
                for (int el = 0; el < 4; el++) {
                    if (k1 == 0)      Aacc[el] = Bacc[el];
                    else if (k1 == 1) Aacc[el] = fmaf(C[el][1], Bacc[el], Aacc[el]);
                    else              Aacc[el] = fmaf(S[el][1], Bacc[el], Aacc[el]);
                }
            }
#pragma unroll
            for (int el = 0; el < 4; el++) {
                if (k0 == 0)      acc[el] = Aacc[el];
                else if (k0 == 1) acc[el] = fmaf(C[el][0], Aacc[el], acc[el]);
                else              acc[el] = fmaf(S[el][0], Aacc[el], acc[el]);
            }
        }
#pragma unroll
        for (int el = 0; el < 4; el++) outv[el][o] = acc[el];
    }

    float4* __restrict__ o4 = (float4*)out;
#pragma unroll
    for (int el = 0; el < 4; el++) {
        long long ei = e0 + el;
        if (ei < B) o4[ei] = make_float4(outv[el][0], outv[el][1], outv[el][2], outv[el][3]);
    }
}

// ---------------------------------------------------------------------------
extern "C" void kernel_launch(void* const* d_in, const int* in_sizes, int n_in,
                              void* d_out, int out_size) {
    const float* xp = (const float*)d_in[0];
    const float* wp = (const float*)d_in[1];
    int sx = in_sizes[0];
    if (n_in >= 2 && in_sizes[0] == 12 && in_sizes[1] != 12) {
        xp = (const float*)d_in[1];
        wp = (const float*)d_in[0];
        sx = in_sizes[1];
    }
    const int B = sx / 4;

    build_T_kernel<<<1, 512>>>(wp);

    const int elems_per_block = 256 * 4;
    const int grid = (B + elems_per_block - 1) / elems_per_block;
    qlayer_kernel<<<grid, 256>>>(xp, (float*)d_out, B);
}

// round 4
// speedup vs baseline: 1.3944x; 1.0013x over previous
#include <cuda_runtime.h>
#include <cuda_bf16.h>
#include <math.h>

// QuantumLayer collapsed to a multilinear polynomial:
//   out_o(x) = T[o] . (1,cos x0,sin x0) x ... x (1,cos x3,sin x3)   (exact identity)
// T (4 x 3^4, batch-constant) built by sampling the circuit at {0,pi/2,pi}^4 and
// applying the inverse 3x3 Vandermonde per axis. Hot kernel: 4 sincos + 320 FMA
// per element — at the FFMA-3reg structural rate this is the fp32 floor.
// R4: R=2 elem/thread + launch_bounds(256,4) for 50% occupancy; __sincosf in build.

__device__ __align__(16) float g_T[432];  // [o][k0][k1][k2][k3 padded to 4]

// ---------------------------------------------------------------------------
// Kernel 1: build T from weights (12 floats). One block.
// ---------------------------------------------------------------------------
__global__ void build_T_kernel(const float* __restrict__ w) {
    __shared__ float bufA[324], bufB[324];
    __shared__ float wc[12], ws[12];
    const int t = threadIdx.x;

    if (t < 12) {
        float s, c;
        __sincosf(0.5f * w[t], &s, &c);
        wc[t] = c; ws[t] = s;
    }
    __syncthreads();

    if (t < 81) {
        // half-angles of sample angles {0, pi/2, pi}
        const float hc[3] = {1.0f, 0.70710678118654752f, 0.0f};
        const float hs[3] = {0.0f, 0.70710678118654752f, 1.0f};
        const int a[4] = {t / 27, (t / 9) % 3, (t / 3) % 3, t % 3};

        float vr[16], vi[16];
#pragma unroll
        for (int i = 0; i < 16; i++) { vr[i] = 0.0f; vi[i] = 0.0f; }
        vr[0] = 1.0f;

        // Initial RX(x_q) at sample angles (qubit q <-> bit 3-q).
#pragma unroll
        for (int q = 0; q < 4; q++) {
            const float cq = hc[a[q]], sq = hs[a[q]];
            const int bit = 1 << (3 - q);
#pragma unroll
            for (int i = 0; i < 16; i++) {
                if (i & bit) continue;
                const int i1 = i | bit;
                float ar = vr[i], ai = vi[i], br = vr[i1], bi = vi[i1];
                vr[i]  = cq * ar + sq * bi;  vi[i]  = cq * ai - sq * br;
                vr[i1] = cq * br + sq * ai;  vi[i1] = cq * bi - sq * ar;
            }
        }
        // 3 layers: RX(w) x4 then CNOT ring.
#pragma unroll
        for (int l = 0; l < 3; l++) {
#pragma unroll
            for (int q = 0; q < 4; q++) {
                const float cq = wc[l * 4 + q], sq = ws[l * 4 + q];
                const int bit = 1 << (3 - q);
#pragma unroll
                for (int i = 0; i < 16; i++) {
                    if (i & bit) continue;
                    const int i1 = i | bit;
                    float ar = vr[i], ai = vi[i], br = vr[i1], bi = vi[i1];
                    vr[i]  = cq * ar + sq * bi;  vi[i]  = cq * ai - sq * br;
                    vr[i1] = cq * br + sq * ai;  vi[i1] = cq * bi - sq * ar;
                }
            }
#pragma unroll
            for (int q = 0; q < 4; q++) {
                const int pcb = 3 - q;
                const int ptb = 3 - ((q + 1) & 3);
#pragma unroll
                for (int i = 0; i < 16; i++) {
                    if (((i >> pcb) & 1) == 0) continue;
                    if ((i >> ptb) & 1) continue;
                    const int i2 = i | (1 << ptb);
                    float tr = vr[i], ti = vi[i];
                    vr[i] = vr[i2]; vi[i] = vi[i2];
                    vr[i2] = tr;    vi[i2] = ti;
                }
            }
        }

        float p[16];
#pragma unroll
        for (int i = 0; i < 16; i++) p[i] = vr[i] * vr[i] + vi[i] * vi[i];
#pragma unroll
        for (int q = 0; q < 4; q++) {
            float s = 0.0f;
#pragma unroll
            for (int i = 0; i < 16; i++)
                s += ((i >> (3 - q)) & 1) ? -p[i] : p[i];
            bufA[q * 81 + t] = s;
        }
    }
    __syncthreads();

    // Inverse Vandermonde for basis (1, cos, sin) at samples {0, pi/2, pi}:
    //   c0 = (s0+s2)/2 ; c1 = (s0-s2)/2 ; c2 = s1 - (s0+s2)/2
    const float Vi[3][3] = {{0.5f, 0.0f, 0.5f},
                            {0.5f, 0.0f, -0.5f},
                            {-0.5f, 1.0f, -0.5f}};
    const int WST[4] = {27, 9, 3, 1};
    float* src = bufA;
    float* dst = bufB;
    for (int ax = 3; ax >= 0; ax--) {
        if (t < 324) {
            const int o = t / 81, e = t % 81;
            const int ws2 = WST[ax];
            const int k = (e / ws2) % 3;
            const int eb = e - k * ws2;
            const float* s = src + o * 81;
            dst[t] = Vi[k][0] * s[eb] + Vi[k][1] * s[eb + ws2] + Vi[k][2] * s[eb + 2 * ws2];
        }
        __syncthreads();
        float* tmp = src; src = dst; dst = tmp;
    }

    if (t < 432) {
        const int o = t / 108, r = t % 108, k012 = r / 4, c = r % 4;
        g_T[t] = (c < 3) ? src[o * 81 + k012 * 3 + c] : 0.0f;
    }
}

// ---------------------------------------------------------------------------
// Kernel 2: 2 elements/thread. Nested Horner contraction, 320 FMA/element.
// ---------------------------------------------------------------------------
__global__ __launch_bounds__(256, 4) void qlayer_kernel(
    const float* __restrict__ x, float* __restrict__ out, int B)
{
    __shared__ __align__(16) float4 shT[108];   // [o*27 + k0*9 + k1*3 + k2], .xyz = k3 coefs
    const int t = threadIdx.x;
    if (t < 108) shT[t] = ((const float4*)g_T)[t];
    __syncthreads();

    const long long e0 = ((long long)blockIdx.x * 256 + t) * 2;
    if (e0 >= B) return;

    const float4* __restrict__ x4 = (const float4*)x;
    float C[2][4], S[2][4];   // [el][qubit], full-angle cos/sin
#pragma unroll
    for (int el = 0; el < 2; el++) {
        long long ei = e0 + el; if (ei >= B) ei = B - 1;
        float4 v = x4[ei];
        __sincosf(v.x, &S[el][0], &C[el][0]);
        __sincosf(v.y, &S[el][1], &C[el][1]);
        __sincosf(v.z, &S[el][2], &C[el][2]);
        __sincosf(v.w, &S[el][3], &C[el][3]);
    }

    float outv[2][4];  // [el][o]
#pragma unroll
    for (int o = 0; o < 4; o++) {
        float acc[2];
#pragma unroll
        for (int k0 = 0; k0 < 3; k0++) {
            float Aacc[2];
#pragma unroll
            for (int k1 = 0; k1 < 3; k1++) {
                float Bacc[2];
#pragma unroll
                for (int k2 = 0; k2 < 3; k2++) {
                    const float4 tq = shT[o * 27 + k0 * 9 + k1 * 3 + k2];
#pragma unroll
                    for (int el = 0; el < 2; el++) {
                        float D = fmaf(tq.z, S[el][3], fmaf(tq.y, C[el][3], tq.x));
                        if (k2 == 0)      Bacc[el] = D;
                        else if (k2 == 1) Bacc[el] = fmaf(C[el][2], D, Bacc[el]);
                        else              Bacc[el] = fmaf(S[el][2], D, Bacc[el]);
                    }
                }
#pragma unroll
                for (int el = 0; el < 2; el++) {
                    if (k1 == 0)      Aacc[el] = Bacc[el];
                    else if (k1 == 1) Aacc[el] = fmaf(C[el][1], Bacc[el], Aacc[el]);
                    else              Aacc[el] = fmaf(S[el][1], Bacc[el], Aacc[el]);
                }
            }
#pragma unroll
            for (int el = 0; el < 2; el++) {
                if (k0 == 0)      acc[el] = Aacc[el];
                else if (k0 == 1) acc[el] = fmaf(C[el][0], Aacc[el], acc[el]);
                else              acc[el] = fmaf(S[el][0], Aacc[el], acc[el]);
            }
        }
#pragma unroll
        for (int el = 0; el < 2; el++) outv[el][o] = acc[el];
    }

    float4* __restrict__ o4 = (float4*)out;
#pragma unroll
    for (int el = 0; el < 2; el++) {
        long long ei = e0 + el;
        if (ei < B) o4[ei] = make_float4(outv[el][0], outv[el][1], outv[el][2], outv[el][3]);
    }
}

// ---------------------------------------------------------------------------
extern "C" void kernel_launch(void* const* d_in, const int* in_sizes, int n_in,
                              void* d_out, int out_size) {
    const float* xp = (const float*)d_in[0];
    const float* wp = (const float*)d_in[1];
    int sx = in_sizes[0];
    if (n_in >= 2 && in_sizes[0] == 12 && in_sizes[1] != 12) {
        xp = (const float*)d_in[1];
        wp = (const float*)d_in[0];
        sx = in_sizes[1];
    }
    const int B = sx / 4;

    build_T_kernel<<<1, 512>>>(wp);

    const int elems_per_block = 256 * 2;
    const int grid = (B + elems_per_block - 1) / elems_per_block;
    qlayer_kernel<<<grid, 256>>>(xp, (float*)d_out, B);
}